// round 12
// baseline (speedup 1.0000x reference)
#include <cuda_runtime.h>
#include <cstdint>

#define S_LEN 2048
#define BATCH 256
#define HID   8
#define NBLK  80
#define OUTSZ 128
#define NROWS (S_LEN*BATCH)   // 524288
#define CH    64
#define NCH   (S_LEN/CH)      // 32
#define NSLOT 3               // xg ring depth (chunks)

struct SM {
    float  xg[NSLOT][CH][128];   // [slot][t_local][bsub*32 + unit*4 + type]  96KB
    float  hring[128][32];       // 16KB, index t&127, [bsub*8+unit]
    float  xbuf[3][32][32];      // 12KB per-worker x staging
    float  wih[32][33];          // padded, pre-scaled
    float  bias[32];
    float4 hw1[NBLK], hw2[NBLK], hb2[NBLK];
    float  hb1[NBLK];
    int    xg_cnt[NCH];
    int    head_cnt[NCH];
    int    lstm_ch;
};

__device__ __forceinline__ float tanha(float x) {
    float r; asm("tanh.approx.f32 %0, %1;" : "=f"(r) : "f"(x)); return r;
}
__device__ __forceinline__ float leaky(float v) { return fmaxf(v, 0.01f * v); }

__global__ void __launch_bounds__(128) kfull(
    const float* __restrict__ x,    const float* __restrict__ h0,
    const float* __restrict__ c0,   const float* __restrict__ w_ih,
    const float* __restrict__ w_hh, const float* __restrict__ b_ih,
    const float* __restrict__ b_hh,
    const float* __restrict__ w_in, const float* __restrict__ b_in,
    const float* __restrict__ rb_w1,const float* __restrict__ rb_b1,
    const float* __restrict__ rb_w2,const float* __restrict__ rb_b2,
    const float* __restrict__ w_bn, const float* __restrict__ b_bn,
    const float* __restrict__ w_out,const float* __restrict__ b_out,
    float* __restrict__ out)
{
    extern __shared__ char smraw[];
    SM* sm = (SM*)smraw;
    const int tid  = threadIdx.x;
    const int lane = tid & 31;
    const int wid  = tid >> 5;
    const int blk  = blockIdx.x;          // CTA owns batches [blk*4, blk*4+4)

    // ---- init (all 4 warps) ----
    for (int idx = tid; idx < 1024; idx += 128) {
        const int g = idx >> 5, j = idx & 31;
        const float s = ((g >> 3) == 2) ? 1.f : 0.5f;
        sm->wih[g][j] = w_ih[idx] * s;
    }
    if (tid < 32) {
        const float s = ((tid >> 3) == 2) ? 1.f : 0.5f;
        sm->bias[tid] = (b_ih[tid] + b_hh[tid]) * s;
        sm->hring[127][tid] = h0[blk * 32 + tid];   // h(-1)
    }
    for (int i = tid; i < NBLK; i += 128) {
        sm->hw1[i] = ((const float4*)rb_w1)[i];
        sm->hw2[i] = ((const float4*)rb_w2)[i];
        sm->hb2[i] = ((const float4*)rb_b2)[i];
        sm->hb1[i] = rb_b1[i];
    }
    if (tid < NCH) { sm->xg_cnt[tid] = 0; sm->head_cnt[tid] = 0; }
    if (tid == 0)  sm->lstm_ch = 0;
    __syncthreads();

    // =====================================================================
    // warp 0: LSTM (SMSP0 exclusive). 4 chains, lane = bsub*8+unit.
    // =====================================================================
    if (wid == 0) {
        const int unit = lane & 7, bsub = lane >> 3;
        float w[4][8];
#pragma unroll
        for (int ty = 0; ty < 4; ty++) {
            const float s = (ty == 2) ? 1.f : 0.5f;
#pragma unroll
            for (int j = 0; j < 8; j++) w[ty][j] = w_hh[(ty * 8 + unit) * 8 + j] * s;
        }
        float h = h0[blk * 32 + lane];
        float c = c0[blk * 32 + lane];
        volatile int* vxg = sm->xg_cnt;
        volatile int* vhd = sm->head_cnt;
        const int xoff = bsub * 32 + unit * 4;

        for (int k = 0; k < NCH; k++) {
            if (lane == 0) {
                while (vxg[k] < 3) __nanosleep(64);
                if (k >= 2) while (vhd[k - 2] < 3) __nanosleep(64);
            }
            __syncwarp();
            __threadfence_block();
            const float (*xgc)[128] = sm->xg[k % NSLOT];
            const int hbase = (k & 1) << 6;
            float4 v = *(const float4*)&xgc[0][xoff];
#pragma unroll 4
            for (int j = 0; j < CH; j++) {
                const float4 vn = *(const float4*)&xgc[(j < CH - 1) ? j + 1 : j][xoff];
                const int hprev = (hbase + j - 1) & 127;
                const float4 hlo = *(const float4*)&sm->hring[hprev][bsub * 8];
                const float4 hhi = *(const float4*)&sm->hring[hprev][bsub * 8 + 4];
                float i0 = v.x, f0 = v.y, g0 = v.z, o0 = v.w;
                float i1 = 0.f, f1 = 0.f, g1 = 0.f, o1 = 0.f;
                f0 = fmaf(w[1][0], hlo.x, f0); f1 = fmaf(w[1][4], hhi.x, f1);
                g0 = fmaf(w[2][0], hlo.x, g0); g1 = fmaf(w[2][4], hhi.x, g1);
                i0 = fmaf(w[0][0], hlo.x, i0); i1 = fmaf(w[0][4], hhi.x, i1);
                o0 = fmaf(w[3][0], hlo.x, o0); o1 = fmaf(w[3][4], hhi.x, o1);
                f0 = fmaf(w[1][1], hlo.y, f0); f1 = fmaf(w[1][5], hhi.y, f1);
                g0 = fmaf(w[2][1], hlo.y, g0); g1 = fmaf(w[2][5], hhi.y, g1);
                i0 = fmaf(w[0][1], hlo.y, i0); i1 = fmaf(w[0][5], hhi.y, i1);
                o0 = fmaf(w[3][1], hlo.y, o0); o1 = fmaf(w[3][5], hhi.y, o1);
                f0 = fmaf(w[1][2], hlo.z, f0); f1 = fmaf(w[1][6], hhi.z, f1);
                g0 = fmaf(w[2][2], hlo.z, g0); g1 = fmaf(w[2][6], hhi.z, g1);
                i0 = fmaf(w[0][2], hlo.z, i0); i1 = fmaf(w[0][6], hhi.z, i1);
                o0 = fmaf(w[3][2], hlo.z, o0); o1 = fmaf(w[3][6], hhi.z, o1);
                f0 = fmaf(w[1][3], hlo.w, f0); f1 = fmaf(w[1][7], hhi.w, f1);
                g0 = fmaf(w[2][3], hlo.w, g0); g1 = fmaf(w[2][7], hhi.w, g1);
                i0 = fmaf(w[0][3], hlo.w, i0); i1 = fmaf(w[0][7], hhi.w, i1);
                o0 = fmaf(w[3][3], hlo.w, o0); o1 = fmaf(w[3][7], hhi.w, o1);
                const float vf = tanha(f0 + f1);
                const float vg = tanha(g0 + g1);
                const float vi = tanha(i0 + i1);
                const float vo = tanha(o0 + o1);
                const float fg = fmaf(vf, 0.5f, 0.5f);
                const float ig = fmaf(vi, 0.5f, 0.5f);
                const float og = fmaf(vo, 0.5f, 0.5f);
                c = fmaf(fg, c, ig * vg);
                h = og * tanha(c);
                sm->hring[hbase + j][lane] = h;
                v = vn;
                __syncwarp();
            }
            __threadfence_block();
            if (lane == 0) *(volatile int*)&sm->lstm_ch = k + 1;
        }
        const size_t fb = (size_t)NROWS * OUTSZ;
        out[fb + blk * 32 + lane] = h;                         // h_f
        out[fb + BATCH * HID + blk * 32 + lane] = c;           // c_f
        return;
    }

    // =====================================================================
    // warps 1-3: workers (SMSP 1/2/3). Per chunk: produce xg (k1 role),
    // consume h -> head + output (k3 role).
    // =====================================================================
    {
        const int my = wid - 1;                 // 0..2
        float wr[32];
#pragma unroll
        for (int j = 0; j < 32; j++) wr[j] = sm->wih[lane][j];
        const float mybias = sm->bias[lane];
        const int ocol = (lane & 7) * 4 + (lane >> 3);

        float win[4][8], bin[4];
#pragma unroll
        for (int i = 0; i < 4; i++) {
            bin[i] = b_in[i];
#pragma unroll
            for (int j = 0; j < 8; j++) win[i][j] = w_in[i * 8 + j];
        }
        const float wbn0 = w_bn[0], wbn1 = w_bn[1];
        const float wbn2 = w_bn[2], wbn3 = w_bn[3], bbn = b_bn[0];
        float4 wo = ((const float4*)w_out)[lane];
        float4 bo = ((const float4*)b_out)[lane];
        wo.x *= .5f; wo.y *= .5f; wo.z *= .5f; wo.w *= .5f;
        bo.x *= .5f; bo.y *= .5f; bo.z *= .5f; bo.w *= .5f;

        volatile int* vch = (volatile int*)&sm->lstm_ch;

        auto produce = [&](int p) {
            float (*xgslot)[128] = sm->xg[p % NSLOT];
            for (int g = my; g < 8; g += 3) {
#pragma unroll 4
                for (int i = 0; i < 32; i++) {
                    const int ri = g * 32 + i;
                    const size_t R = (size_t)(p * CH + (ri >> 2)) * BATCH
                                   + blk * 4 + (ri & 3);
                    sm->xbuf[my][i][lane] = x[R * 32 + lane];
                }
                __syncwarp();
                for (int i = 0; i < 32; i++) {
                    const int ri = g * 32 + i;
                    const float4* xr = (const float4*)&sm->xbuf[my][i][0];
                    float a0 = mybias, a1 = 0.f, a2 = 0.f, a3 = 0.f;
#pragma unroll
                    for (int j4 = 0; j4 < 8; j4++) {
                        const float4 vv = xr[j4];
                        a0 = fmaf(wr[j4 * 4 + 0], vv.x, a0);
                        a1 = fmaf(wr[j4 * 4 + 1], vv.y, a1);
                        a2 = fmaf(wr[j4 * 4 + 2], vv.z, a2);
                        a3 = fmaf(wr[j4 * 4 + 3], vv.w, a3);
                    }
                    xgslot[ri >> 2][(ri & 3) * 32 + ocol] = (a0 + a1) + (a2 + a3);
                }
                __syncwarp();
            }
            __threadfence_block();
            if (lane == 0) atomicAdd(&sm->xg_cnt[p], 1);
        };

        auto head = [&](int q) {
            for (int g = my; g < 8; g += 3) {
                const int ri = g * 32 + lane;
                const int hs = (q * CH + (ri >> 2)) & 127;
                const float4 ha = *(const float4*)&sm->hring[hs][(ri & 3) * 8];
                const float4 hb = *(const float4*)&sm->hring[hs][(ri & 3) * 8 + 4];
                const float hv[8] = {ha.x, ha.y, ha.z, ha.w,
                                     hb.x, hb.y, hb.z, hb.w};
                float y[4];
#pragma unroll
                for (int i = 0; i < 4; i++) {
                    float a = bin[i];
#pragma unroll
                    for (int j = 0; j < 8; j++) a = fmaf(win[i][j], hv[j], a);
                    y[i] = leaky(a);
                }
#pragma unroll 2
                for (int bb = 0; bb < NBLK; bb++) {
                    const float4 w1 = sm->hw1[bb];
                    const float4 w2 = sm->hw2[bb];
                    const float4 b2 = sm->hb2[bb];
                    float z = sm->hb1[bb];
                    z = fmaf(w1.x, y[0], z);
                    z = fmaf(w1.y, y[1], z);
                    z = fmaf(w1.z, y[2], z);
                    z = fmaf(w1.w, y[3], z);
                    z = leaky(z);
                    y[0] = leaky(fmaf(w2.x, z, y[0]) + b2.x);
                    y[1] = leaky(fmaf(w2.y, z, y[1]) + b2.y);
                    y[2] = leaky(fmaf(w2.z, z, y[2]) + b2.z);
                    y[3] = leaky(fmaf(w2.w, z, y[3]) + b2.w);
                }
                float yb = bbn;
                yb = fmaf(wbn0, y[0], yb);
                yb = fmaf(wbn1, y[1], yb);
                yb = fmaf(wbn2, y[2], yb);
                yb = fmaf(wbn3, y[3], yb);
                yb = leaky(yb);
#pragma unroll
                for (int cidx = 0; cidx < 32; cidx++) {
                    const float ybc = __shfl_sync(0xffffffffu, yb, cidx);
                    const int rc = g * 32 + cidx;
                    const size_t row = (size_t)(q * CH + (rc >> 2)) * BATCH
                                     + blk * 4 + (rc & 3);
                    float4 o;
                    o.x = fmaf(tanha(fmaf(ybc, wo.x, bo.x)), .5f, .5f);
                    o.y = fmaf(tanha(fmaf(ybc, wo.y, bo.y)), .5f, .5f);
                    o.z = fmaf(tanha(fmaf(ybc, wo.z, bo.z)), .5f, .5f);
                    o.w = fmaf(tanha(fmaf(ybc, wo.w, bo.w)), .5f, .5f);
                    *(float4*)(out + row * OUTSZ + lane * 4) = o;
                }
            }
            __threadfence_block();
            if (lane == 0) atomicAdd(&sm->head_cnt[q], 1);
        };

        produce(0);
        produce(1);
        produce(2);
        for (int p = 3; p < NCH; p++) {
            if (lane == 0) { while (*vch < p - 2) __nanosleep(128); }
            __syncwarp();
            __threadfence_block();
            head(p - 3);
            produce(p);
        }
        for (int q = NCH - 3; q < NCH; q++) {
            if (lane == 0) { while (*vch < q + 1) __nanosleep(128); }
            __syncwarp();
            __threadfence_block();
            head(q);
        }
    }
}

// ---------------------------------------------------------------------------
extern "C" void kernel_launch(void* const* d_in, const int* in_sizes, int n_in,
                              void* d_out, int out_size)
{
    const float* x     = (const float*)d_in[0];
    const float* h     = (const float*)d_in[1];
    const float* c     = (const float*)d_in[2];
    const float* w_ih  = (const float*)d_in[3];
    const float* w_hh  = (const float*)d_in[4];
    const float* b_ih  = (const float*)d_in[5];
    const float* b_hh  = (const float*)d_in[6];
    const float* w_in  = (const float*)d_in[7];
    const float* b_in  = (const float*)d_in[8];
    const float* rb_w1 = (const float*)d_in[9];
    const float* rb_b1 = (const float*)d_in[10];
    const float* rb_w2 = (const float*)d_in[11];
    const float* rb_b2 = (const float*)d_in[12];
    const float* w_bn  = (const float*)d_in[13];
    const float* b_bn  = (const float*)d_in[14];
    const float* w_out = (const float*)d_in[15];
    const float* b_out = (const float*)d_in[16];
    float* out = (float*)d_out;

    cudaFuncSetAttribute(kfull, cudaFuncAttributeMaxDynamicSharedMemorySize,
                         (int)sizeof(SM));
    kfull<<<64, 128, sizeof(SM)>>>(x, h, c, w_ih, w_hh, b_ih, b_hh,
                                   w_in, b_in, rb_w1, rb_b1, rb_w2, rb_b2,
                                   w_bn, b_bn, w_out, b_out, out);
}

// round 15
// speedup vs baseline: 3.6820x; 3.6820x over previous
#include <cuda_runtime.h>
#include <cstdint>

#define S_LEN 2048
#define BATCH 256
#define HID   8
#define NBLK  80
#define OUTSZ 128
#define NROWS (S_LEN*BATCH)   // 524288
#define CHUNK_T 128
#define NCHUNK  (S_LEN/CHUNK_T)   // 16
#define K2_CTAS 64
#define PF 8

// Scratch (__device__ globals; no runtime allocation)
// g_xg layout: [row][unit*4 + gate_type], row = t*BATCH + b
__device__ float g_xg[(size_t)NROWS * 32];   // 64 MB
__device__ float g_ys[(size_t)NROWS * HID];  // 16 MB
__device__ int   g_flag[NCHUNK];

__device__ __forceinline__ float tanha(float x) {
    float r; asm("tanh.approx.f32 %0, %1;" : "=f"(r) : "f"(x)); return r;
}
__device__ __forceinline__ float leaky(float v) { return fmaxf(v, 0.01f * v); }
__device__ __forceinline__ int ld_acq(const int* p) {
    int v;
    asm volatile("ld.acquire.gpu.global.u32 %0, [%1];" : "=r"(v) : "l"(p));
    return v;
}

__global__ void k0_reset() {
    if (threadIdx.x < NCHUNK) g_flag[threadIdx.x] = 0;
}

// ---------------------------------------------------------------------------
// Fused k1 (producer CTAs, bids >= 64) + k2 (LSTM CTAs, bids 0..63).
// 128KB dynamic smem forces 1 CTA/SM: k1 CTAs can never co-reside with a
// k2 CTA and steal its SMSP issue slots. k2 gates per 128-step chunk on
// g_flag (64 pollers, ld.acquire + nanosleep -- no atomic storm).
// ---------------------------------------------------------------------------
__global__ void __launch_bounds__(256) k12(
    const float* __restrict__ x,    const float* __restrict__ h0,
    const float* __restrict__ c0,   const float* __restrict__ w_ih,
    const float* __restrict__ w_hh, const float* __restrict__ b_ih,
    const float* __restrict__ b_hh, float* __restrict__ out)
{
    extern __shared__ char smraw[];
    const int bid  = blockIdx.x;
    const int tid  = threadIdx.x;
    const int lane = tid & 31;
    const int wid  = tid >> 5;

    // =====================================================================
    // K1 role: one CTA per timestep t. Writes xg for all 256 batches of t.
    // xg[row][u*4+ty] = s(ty) * ( x[row].w_ih[ty*8+u] + b_ih + b_hh )
    // =====================================================================
    if (bid >= K2_CTAS) {
        const int t = bid - K2_CTAS;
        float4* sx  = (float4*)smraw;                 // 256 rows of x (32KB)
        float*  swp = (float*)(smraw + 32768);        // 32*33 padded weights

#pragma unroll
        for (int k = 0; k < 4; k++) {
            const int idx = tid + k * 256;            // 1024 floats
            const int g = idx >> 5, j = idx & 31;
            const float s = ((g >> 3) == 2) ? 1.f : 0.5f;
            swp[g * 33 + j] = w_ih[idx] * s;
        }

        const size_t rowbase = (size_t)t * 256;
        const float4* xg4 = (const float4*)x + rowbase * 8;
#pragma unroll
        for (int i = 0; i < 8; i++) sx[tid + i * 256] = xg4[tid + i * 256];

        __syncthreads();

        float w[32];
#pragma unroll
        for (int j = 0; j < 32; j++) w[j] = swp[lane * 33 + j];
        const float s2 = ((lane >> 3) == 2) ? 1.f : 0.5f;
        const float bias = (b_ih[lane] + b_hh[lane]) * s2;

        const int ocol = (lane & 7) * 4 + (lane >> 3);    // unit-major column
        float* op = g_xg + (rowbase + wid * 32) * 32 + ocol;
        const float4* xr0 = &sx[wid * 32 * 8];

#pragma unroll 4
        for (int r = 0; r < 32; r++) {
            const float4* xr = xr0 + r * 8;
            float a0 = bias, a1 = 0.f, a2 = 0.f, a3 = 0.f;
#pragma unroll
            for (int j4 = 0; j4 < 8; j4++) {
                const float4 v = xr[j4];                  // broadcast LDS.128
                a0 = fmaf(w[j4 * 4 + 0], v.x, a0);
                a1 = fmaf(w[j4 * 4 + 1], v.y, a1);
                a2 = fmaf(w[j4 * 4 + 2], v.z, a2);
                a3 = fmaf(w[j4 * 4 + 3], v.w, a3);
            }
            op[(size_t)r * 32] = (a0 + a1) + (a2 + a3);   // coalesced STG.32
        }

        __syncthreads();
        if (tid == 0) { __threadfence(); atomicAdd(&g_flag[t >> 7], 1); }
        return;
    }

    // =====================================================================
    // K2 role: sequential LSTM, 1 warp/CTA, 4 chains (lane = bsub*8+unit),
    // each lane computes all 4 gates of its unit; h-exchange via smem.
    // Byte-identical inner loop to the proven round-7 kernel.
    // =====================================================================
    if (wid != 0) return;
    float* sh = (float*)smraw;              // sh[2][32]

    const int blk  = bid;                   // 0..63
    const int unit = lane & 7;
    const int bsub = lane >> 3;

    float w[4][8];
#pragma unroll
    for (int ty = 0; ty < 4; ty++) {
        const float s = (ty == 2) ? 1.f : 0.5f;
#pragma unroll
        for (int j = 0; j < 8; j++) w[ty][j] = w_hh[(ty * 8 + unit) * 8 + j] * s;
    }

    float h = h0[blk * 32 + lane];
    float c = c0[blk * 32 + lane];

    const float4* xp = (const float4*)g_xg + (size_t)blk * 32 + lane;
    float* yp = g_ys + blk * 32 + lane;             // + t*2048

    sh[lane] = h;           // buffer parity 0
    __syncwarp();

    float4 buf[PF];

#define K2_STEP(T2, K)                                                        \
    {                                                                         \
        const float4 xg  = buf[K];                                            \
        const float4 hlo = *(const float4*)&sh[((K) & 1) * 32 + bsub * 8];    \
        const float4 hhi = *(const float4*)&sh[((K) & 1) * 32 + bsub * 8 + 4];\
        float i0 = xg.x, f0 = xg.y, gg0 = xg.z, o0 = xg.w;                    \
        float i1 = 0.f, f1 = 0.f, gg1 = 0.f, o1 = 0.f;                        \
        f0  = fmaf(w[1][0], hlo.x, f0);  f1  = fmaf(w[1][4], hhi.x, f1);      \
        gg0 = fmaf(w[2][0], hlo.x, gg0); gg1 = fmaf(w[2][4], hhi.x, gg1);     \
        i0  = fmaf(w[0][0], hlo.x, i0);  i1  = fmaf(w[0][4], hhi.x, i1);      \
        o0  = fmaf(w[3][0], hlo.x, o0);  o1  = fmaf(w[3][4], hhi.x, o1);      \
        f0  = fmaf(w[1][1], hlo.y, f0);  f1  = fmaf(w[1][5], hhi.y, f1);      \
        gg0 = fmaf(w[2][1], hlo.y, gg0); gg1 = fmaf(w[2][5], hhi.y, gg1);     \
        i0  = fmaf(w[0][1], hlo.y, i0);  i1  = fmaf(w[0][5], hhi.y, i1);      \
        o0  = fmaf(w[3][1], hlo.y, o0);  o1  = fmaf(w[3][5], hhi.y, o1);      \
        f0  = fmaf(w[1][2], hlo.z, f0);  f1  = fmaf(w[1][6], hhi.z, f1);      \
        gg0 = fmaf(w[2][2], hlo.z, gg0); gg1 = fmaf(w[2][6], hhi.z, gg1);     \
        i0  = fmaf(w[0][2], hlo.z, i0);  i1  = fmaf(w[0][6], hhi.z, i1);      \
        o0  = fmaf(w[3][2], hlo.z, o0);  o1  = fmaf(w[3][6], hhi.z, o1);      \
        f0  = fmaf(w[1][3], hlo.w, f0);  f1  = fmaf(w[1][7], hhi.w, f1);      \
        gg0 = fmaf(w[2][3], hlo.w, gg0); gg1 = fmaf(w[2][7], hhi.w, gg1);     \
        i0  = fmaf(w[0][3], hlo.w, i0);  i1  = fmaf(w[0][7], hhi.w, i1);      \
        o0  = fmaf(w[3][3], hlo.w, o0);  o1  = fmaf(w[3][7], hhi.w, o1);      \
        const float vf = tanha(f0 + f1);                                      \
        const float vg = tanha(gg0 + gg1);                                    \
        const float vi = tanha(i0 + i1);                                      \
        const float vo = tanha(o0 + o1);                                      \
        const float fg = fmaf(vf, 0.5f, 0.5f);                                \
        const float ig = fmaf(vi, 0.5f, 0.5f);                                \
        const float og = fmaf(vo, 0.5f, 0.5f);                                \
        c = fmaf(fg, c, ig * vg);                                             \
        h = og * tanha(c);                                                    \
        sh[(((K) & 1) ^ 1) * 32 + lane] = h;                                  \
        yp[(size_t)(T2) * 2048] = h;                                          \
        int pfT = (T2) + PF; if (pfT >= S_LEN) pfT = S_LEN - 1;               \
        buf[K] = __ldg(xp + (size_t)pfT * 2048);                              \
        __syncwarp();                                                         \
    }

    for (int ch = 0; ch < NCHUNK; ch++) {
        // gate: chunk ch AND ch+1 ready (prefetch reaches into ch+1)
        if (lane == 0) {
            while (ld_acq(&g_flag[ch]) < CHUNK_T) __nanosleep(128);
            if (ch + 1 < NCHUNK)
                while (ld_acq(&g_flag[ch + 1]) < CHUNK_T) __nanosleep(128);
        }
        __syncwarp();

        if (ch == 0) {
#pragma unroll
            for (int k = 0; k < PF; k++)
                buf[k] = __ldg(xp + (size_t)k * 2048);
        }

        const int tbase = ch * CHUNK_T;
#pragma unroll 1
        for (int j = 0; j < CHUNK_T / PF; j++) {
            const int t0 = tbase + j * PF;
            K2_STEP(t0 + 0, 0) K2_STEP(t0 + 1, 1)
            K2_STEP(t0 + 2, 2) K2_STEP(t0 + 3, 3)
            K2_STEP(t0 + 4, 4) K2_STEP(t0 + 5, 5)
            K2_STEP(t0 + 6, 6) K2_STEP(t0 + 7, 7)
        }
    }

    const size_t fb = (size_t)NROWS * OUTSZ;
    out[fb + blk * 32 + lane] = h;                          // h_f
    out[fb + BATCH * HID + blk * 32 + lane] = c;            // c_f
}

// ---------------------------------------------------------------------------
// K3: residual MLP head (unchanged round-7 kernel, separate serial launch).
// ---------------------------------------------------------------------------
__global__ void __launch_bounds__(256) k3_res(
    const float* __restrict__ w_in,  const float* __restrict__ b_in,
    const float* __restrict__ rb_w1, const float* __restrict__ rb_b1,
    const float* __restrict__ rb_w2, const float* __restrict__ rb_b2,
    const float* __restrict__ w_bn,  const float* __restrict__ b_bn,
    const float* __restrict__ w_out, const float* __restrict__ b_out,
    float* __restrict__ out)
{
    __shared__ float4 s_w1[NBLK], s_w2[NBLK], s_b2[NBLK];
    __shared__ float  s_b1[NBLK];
    for (int i = threadIdx.x; i < NBLK; i += blockDim.x) {
        s_w1[i] = ((const float4*)rb_w1)[i];
        s_w2[i] = ((const float4*)rb_w2)[i];
        s_b2[i] = ((const float4*)rb_b2)[i];
        s_b1[i] = rb_b1[i];
    }
    __syncthreads();

    const int lane  = threadIdx.x & 31;
    const int warpg = (blockIdx.x * blockDim.x + threadIdx.x) >> 5;
    const int base  = warpg * 32;           // 16384 warps cover 524288 rows
    const int e     = base + lane;

    const float4 ha = *(const float4*)(g_ys + (size_t)e * 8);
    const float4 hb = *(const float4*)(g_ys + (size_t)e * 8 + 4);
    const float hv[8] = {ha.x, ha.y, ha.z, ha.w, hb.x, hb.y, hb.z, hb.w};

    float y[4];
#pragma unroll
    for (int i = 0; i < 4; i++) {
        float a = b_in[i];
#pragma unroll
        for (int j = 0; j < 8; j++) a = fmaf(w_in[i * 8 + j], hv[j], a);
        y[i] = leaky(a);
    }

#pragma unroll 2
    for (int blk = 0; blk < NBLK; blk++) {
        const float4 w1 = s_w1[blk];
        const float4 w2 = s_w2[blk];
        const float4 b2 = s_b2[blk];
        float z = s_b1[blk];
        z = fmaf(w1.x, y[0], z);
        z = fmaf(w1.y, y[1], z);
        z = fmaf(w1.z, y[2], z);
        z = fmaf(w1.w, y[3], z);
        z = leaky(z);
        y[0] = leaky(fmaf(w2.x, z, y[0]) + b2.x);
        y[1] = leaky(fmaf(w2.y, z, y[1]) + b2.y);
        y[2] = leaky(fmaf(w2.z, z, y[2]) + b2.z);
        y[3] = leaky(fmaf(w2.w, z, y[3]) + b2.w);
    }

    float yb = b_bn[0];
    yb = fmaf(w_bn[0], y[0], yb);
    yb = fmaf(w_bn[1], y[1], yb);
    yb = fmaf(w_bn[2], y[2], yb);
    yb = fmaf(w_bn[3], y[3], yb);
    yb = leaky(yb);

    // sigmoid(a*w+b) = 0.5 + 0.5*tanh(0.5*(a*w+b)) -> pre-halved w,b
    float4 wo = *(const float4*)(w_out + lane * 4);
    float4 bo = *(const float4*)(b_out + lane * 4);
    wo.x *= 0.5f; wo.y *= 0.5f; wo.z *= 0.5f; wo.w *= 0.5f;
    bo.x *= 0.5f; bo.y *= 0.5f; bo.z *= 0.5f; bo.w *= 0.5f;
    float* op = out + (size_t)base * OUTSZ + lane * 4;

#pragma unroll
    for (int cidx = 0; cidx < 32; cidx++) {
        const float ybc = __shfl_sync(0xffffffffu, yb, cidx);
        float4 o;
        o.x = fmaf(tanha(fmaf(ybc, wo.x, bo.x)), 0.5f, 0.5f);
        o.y = fmaf(tanha(fmaf(ybc, wo.y, bo.y)), 0.5f, 0.5f);
        o.z = fmaf(tanha(fmaf(ybc, wo.z, bo.z)), 0.5f, 0.5f);
        o.w = fmaf(tanha(fmaf(ybc, wo.w, bo.w)), 0.5f, 0.5f);
        *(float4*)(op + (size_t)cidx * OUTSZ) = o;
    }
}

// ---------------------------------------------------------------------------
extern "C" void kernel_launch(void* const* d_in, const int* in_sizes, int n_in,
                              void* d_out, int out_size)
{
    const float* x     = (const float*)d_in[0];
    const float* h     = (const float*)d_in[1];
    const float* c     = (const float*)d_in[2];
    const float* w_ih  = (const float*)d_in[3];
    const float* w_hh  = (const float*)d_in[4];
    const float* b_ih  = (const float*)d_in[5];
    const float* b_hh  = (const float*)d_in[6];
    const float* w_in  = (const float*)d_in[7];
    const float* b_in  = (const float*)d_in[8];
    const float* rb_w1 = (const float*)d_in[9];
    const float* rb_b1 = (const float*)d_in[10];
    const float* rb_w2 = (const float*)d_in[11];
    const float* rb_b2 = (const float*)d_in[12];
    const float* w_bn  = (const float*)d_in[13];
    const float* b_bn  = (const float*)d_in[14];
    const float* w_out = (const float*)d_in[15];
    const float* b_out = (const float*)d_in[16];
    float* out = (float*)d_out;

    static bool attr_set = false;
    if (!attr_set) {
        cudaFuncSetAttribute(k12, cudaFuncAttributeMaxDynamicSharedMemorySize,
                             131072);
        attr_set = true;
    }

    k0_reset<<<1, 32>>>();
    k12<<<K2_CTAS + S_LEN, 256, 131072>>>(x, h, c, w_ih, w_hh, b_ih, b_hh, out);
    k3_res<<<2048, 256>>>(w_in, b_in, rb_w1, rb_b1, rb_w2, rb_b2,
                          w_bn, b_bn, w_out, b_out, out);
}

// round 17
// speedup vs baseline: 9.0951x; 2.4702x over previous
#include <cuda_runtime.h>
#include <cstdint>

#define S_LEN 2048
#define BATCH 256
#define HID   8
#define NBLK  80
#define OUTSZ 128
#define NROWS (S_LEN*BATCH)   // 524288
#define PF 8

// Scratch (__device__ globals; no runtime allocation)
// g_xg layout: [row][unit*4 + gate_type], row = t*BATCH + b ; padded PF rows
__device__ float g_xg[((size_t)NROWS + PF * BATCH) * 32];
// g_ys layout: [t/4][blk(64)][lane(32)][4 sub-steps]  (float4 per (slot,blk,lane))
__device__ float g_ys[(size_t)NROWS * HID];  // 16 MB

__device__ __forceinline__ float tanha(float x) {
    float r; asm("tanh.approx.f32 %0, %1;" : "=f"(r) : "f"(x)); return r;
}
__device__ __forceinline__ float leaky(float v) { return fmaxf(v, 0.01f * v); }

// ---------------------------------------------------------------------------
// K1: xg[row][u*4+ty] = s(ty) * ( x[row].w_ih[ty*8+u] + b_ih + b_hh )
//     s = 0.5 for sigmoid gates (i,f,o), 1.0 for tanh gate. (round-3 proven)
// ---------------------------------------------------------------------------
__global__ void __launch_bounds__(256) k1_xw(
    const float* __restrict__ x, const float* __restrict__ w_ih,
    const float* __restrict__ b_ih, const float* __restrict__ b_hh)
{
    __shared__ float4 sx[256 * 8];     // 32 KB: 256 rows of x
    __shared__ float  swp[32 * 33];    // padded weights

    const int tid  = threadIdx.x;
    const int lane = tid & 31;
    const int wid  = tid >> 5;

#pragma unroll
    for (int k = 0; k < 4; k++) {
        const int idx = tid + k * 256;          // 1024 floats
        const int g = idx >> 5, j = idx & 31;
        const float s = ((g >> 3) == 2) ? 1.f : 0.5f;
        swp[g * 33 + j] = w_ih[idx] * s;
    }

    const size_t rowbase = (size_t)blockIdx.x * 256;
    const float4* xg4 = (const float4*)x + rowbase * 8;
#pragma unroll
    for (int i = 0; i < 8; i++) sx[tid + i * 256] = xg4[tid + i * 256];

    __syncthreads();

    float w[32];
#pragma unroll
    for (int j = 0; j < 32; j++) w[j] = swp[lane * 33 + j];
    const float s2 = ((lane >> 3) == 2) ? 1.f : 0.5f;
    const float bias = (b_ih[lane] + b_hh[lane]) * s2;

    const int ocol = (lane & 7) * 4 + (lane >> 3);   // unit-major column

    float* op = g_xg + (rowbase + wid * 32) * 32 + ocol;
    const float4* xr0 = &sx[wid * 32 * 8];

#pragma unroll 4
    for (int r = 0; r < 32; r++) {
        const float4* xr = xr0 + r * 8;
        float a0 = bias, a1 = 0.f, a2 = 0.f, a3 = 0.f;
#pragma unroll
        for (int j4 = 0; j4 < 8; j4++) {
            const float4 v = xr[j4];            // broadcast LDS.128
            a0 = fmaf(w[j4 * 4 + 0], v.x, a0);
            a1 = fmaf(w[j4 * 4 + 1], v.y, a1);
            a2 = fmaf(w[j4 * 4 + 2], v.z, a2);
            a3 = fmaf(w[j4 * 4 + 3], v.w, a3);
        }
        op[(size_t)r * 32] = (a0 + a1) + (a2 + a3);   // coalesced STG.32
    }
}

// ---------------------------------------------------------------------------
// K2: sequential LSTM, 1 warp/CTA, 4 chains (lane = bsub*8+unit); each lane
//     computes all 4 gates of its unit; h-exchange via double-buffered smem.
//     NEW: h output batched in registers, one STG.128 per 4 steps; prefetch
//     clamp removed via padded g_xg.
// ---------------------------------------------------------------------------
__global__ void __launch_bounds__(32, 1) k2_lstm(
    const float* __restrict__ h0, const float* __restrict__ c0,
    const float* __restrict__ w_hh, float* __restrict__ out)
{
    __shared__ __align__(16) float sh[2][32];

    const int lane = threadIdx.x;
    const int blk  = blockIdx.x;           // 64 blocks, 4 batch elems each
    const int unit = lane & 7;
    const int bsub = lane >> 3;

    float w[4][8];
#pragma unroll
    for (int ty = 0; ty < 4; ty++) {
        const float s = (ty == 2) ? 1.f : 0.5f;
#pragma unroll
        for (int j = 0; j < 8; j++) w[ty][j] = w_hh[(ty * 8 + unit) * 8 + j] * s;
    }

    float h = h0[blk * 32 + lane];
    float c = c0[blk * 32 + lane];

    const float4* xp = (const float4*)g_xg + (size_t)blk * 32 + lane;
    float4* yq = (float4*)g_ys + blk * 32 + lane;   // + (t>>2)*2048

    sh[0][lane] = h;
    __syncwarp();

    float4 buf[PF];
    float4 hq;
#pragma unroll
    for (int k = 0; k < PF; k++) buf[k] = __ldg(xp + (size_t)k * 2048);

#define K2_STEP(T2, K)                                                        \
    {                                                                         \
        const float4 xg  = buf[K];                                            \
        const float4 hlo = *(const float4*)&sh[(K) & 1][bsub * 8];            \
        const float4 hhi = *(const float4*)&sh[(K) & 1][bsub * 8 + 4];        \
        float i0 = xg.x, f0 = xg.y, gg0 = xg.z, o0 = xg.w;                    \
        float i1 = 0.f, f1 = 0.f, gg1 = 0.f, o1 = 0.f;                        \
        f0  = fmaf(w[1][0], hlo.x, f0);  f1  = fmaf(w[1][4], hhi.x, f1);      \
        gg0 = fmaf(w[2][0], hlo.x, gg0); gg1 = fmaf(w[2][4], hhi.x, gg1);     \
        i0  = fmaf(w[0][0], hlo.x, i0);  i1  = fmaf(w[0][4], hhi.x, i1);      \
        o0  = fmaf(w[3][0], hlo.x, o0);  o1  = fmaf(w[3][4], hhi.x, o1);      \
        f0  = fmaf(w[1][1], hlo.y, f0);  f1  = fmaf(w[1][5], hhi.y, f1);      \
        gg0 = fmaf(w[2][1], hlo.y, gg0); gg1 = fmaf(w[2][5], hhi.y, gg1);     \
        i0  = fmaf(w[0][1], hlo.y, i0);  i1  = fmaf(w[0][5], hhi.y, i1);      \
        o0  = fmaf(w[3][1], hlo.y, o0);  o1  = fmaf(w[3][5], hhi.y, o1);      \
        f0  = fmaf(w[1][2], hlo.z, f0);  f1  = fmaf(w[1][6], hhi.z, f1);      \
        gg0 = fmaf(w[2][2], hlo.z, gg0); gg1 = fmaf(w[2][6], hhi.z, gg1);     \
        i0  = fmaf(w[0][2], hlo.z, i0);  i1  = fmaf(w[0][6], hhi.z, i1);      \
        o0  = fmaf(w[3][2], hlo.z, o0);  o1  = fmaf(w[3][6], hhi.z, o1);      \
        f0  = fmaf(w[1][3], hlo.w, f0);  f1  = fmaf(w[1][7], hhi.w, f1);      \
        gg0 = fmaf(w[2][3], hlo.w, gg0); gg1 = fmaf(w[2][7], hhi.w, gg1);     \
        i0  = fmaf(w[0][3], hlo.w, i0);  i1  = fmaf(w[0][7], hhi.w, i1);      \
        o0  = fmaf(w[3][3], hlo.w, o0);  o1  = fmaf(w[3][7], hhi.w, o1);      \
        const float vf = tanha(f0 + f1);                                      \
        const float vg = tanha(gg0 + gg1);                                    \
        const float vi = tanha(i0 + i1);                                      \
        const float vo = tanha(o0 + o1);                                      \
        const float fg = fmaf(vf, 0.5f, 0.5f);                                \
        const float ig = fmaf(vi, 0.5f, 0.5f);                                \
        const float og = fmaf(vo, 0.5f, 0.5f);                                \
        c = fmaf(fg, c, ig * vg);                                             \
        h = og * tanha(c);                                                    \
        sh[((K) & 1) ^ 1][lane] = h;                                          \
        (&hq.x)[(K) & 3] = h;                                                 \
        if (((K) & 3) == 3)                                                   \
            yq[(size_t)((T2) >> 2) * 2048] = hq;                              \
        buf[K] = __ldg(xp + (size_t)((T2) + PF) * 2048);                      \
        __syncwarp();                                                         \
    }

#pragma unroll 1
    for (int t = 0; t < S_LEN; t += PF) {
        K2_STEP(t + 0, 0) K2_STEP(t + 1, 1)
        K2_STEP(t + 2, 2) K2_STEP(t + 3, 3)
        K2_STEP(t + 4, 4) K2_STEP(t + 5, 5)
        K2_STEP(t + 6, 6) K2_STEP(t + 7, 7)
    }

    const size_t fb = (size_t)NROWS * OUTSZ;
    out[fb + blk * 32 + lane] = h;                          // h_f
    out[fb + BATCH * HID + blk * 32 + lane] = c;            // c_f
}

// ---------------------------------------------------------------------------
// K3: residual MLP head. Lane per (t,b) row; h loaded from the k2-batched
//     layout (8 x LDG.32); warp-transpose shfl for the 128-wide expansion.
// ---------------------------------------------------------------------------
__global__ void __launch_bounds__(256) k3_res(
    const float* __restrict__ w_in,  const float* __restrict__ b_in,
    const float* __restrict__ rb_w1, const float* __restrict__ rb_b1,
    const float* __restrict__ rb_w2, const float* __restrict__ rb_b2,
    const float* __restrict__ w_bn,  const float* __restrict__ b_bn,
    const float* __restrict__ w_out, const float* __restrict__ b_out,
    float* __restrict__ out)
{
    __shared__ float4 s_w1[NBLK], s_w2[NBLK], s_b2[NBLK];
    __shared__ float  s_b1[NBLK];
    for (int i = threadIdx.x; i < NBLK; i += blockDim.x) {
        s_w1[i] = ((const float4*)rb_w1)[i];
        s_w2[i] = ((const float4*)rb_w2)[i];
        s_b2[i] = ((const float4*)rb_b2)[i];
        s_b1[i] = rb_b1[i];
    }
    __syncthreads();

    const int lane  = threadIdx.x & 31;
    const int warpg = (blockIdx.x * blockDim.x + threadIdx.x) >> 5;
    const int base  = warpg * 32;           // 16384 warps cover 524288 rows
    const int e     = base + lane;
    const int t     = e >> 8;               // row = t*256 + b
    const int b     = e & 255;

    // h[u] at g_ys[((t>>2)*2048 + (b>>2)*32 + (b&3)*8 + u)*4 + (t&3)]
    const float* hp = g_ys
        + (((size_t)(t >> 2) * 2048 + (b >> 2) * 32 + (b & 3) * 8) << 2)
        + (t & 3);
    float hv[8];
#pragma unroll
    for (int u = 0; u < 8; u++) hv[u] = hp[u * 4];

    float y[4];
#pragma unroll
    for (int i = 0; i < 4; i++) {
        float a = b_in[i];
#pragma unroll
        for (int j = 0; j < 8; j++) a = fmaf(w_in[i * 8 + j], hv[j], a);
        y[i] = leaky(a);
    }

#pragma unroll 2
    for (int blk = 0; blk < NBLK; blk++) {
        const float4 w1 = s_w1[blk];
        const float4 w2 = s_w2[blk];
        const float4 b2 = s_b2[blk];
        float z = s_b1[blk];
        z = fmaf(w1.x, y[0], z);
        z = fmaf(w1.y, y[1], z);
        z = fmaf(w1.z, y[2], z);
        z = fmaf(w1.w, y[3], z);
        z = leaky(z);
        y[0] = leaky(fmaf(w2.x, z, y[0]) + b2.x);
        y[1] = leaky(fmaf(w2.y, z, y[1]) + b2.y);
        y[2] = leaky(fmaf(w2.z, z, y[2]) + b2.z);
        y[3] = leaky(fmaf(w2.w, z, y[3]) + b2.w);
    }

    float yb = b_bn[0];
    yb = fmaf(w_bn[0], y[0], yb);
    yb = fmaf(w_bn[1], y[1], yb);
    yb = fmaf(w_bn[2], y[2], yb);
    yb = fmaf(w_bn[3], y[3], yb);
    yb = leaky(yb);

    // sigmoid(a*w+b) = 0.5 + 0.5*tanh(0.5*(a*w+b)) -> pre-halved w,b
    float4 wo = *(const float4*)(w_out + lane * 4);
    float4 bo = *(const float4*)(b_out + lane * 4);
    wo.x *= 0.5f; wo.y *= 0.5f; wo.z *= 0.5f; wo.w *= 0.5f;
    bo.x *= 0.5f; bo.y *= 0.5f; bo.z *= 0.5f; bo.w *= 0.5f;
    float* op = out + (size_t)base * OUTSZ + lane * 4;

#pragma unroll
    for (int cidx = 0; cidx < 32; cidx++) {
        const float ybc = __shfl_sync(0xffffffffu, yb, cidx);
        float4 o;
        o.x = fmaf(tanha(fmaf(ybc, wo.x, bo.x)), 0.5f, 0.5f);
        o.y = fmaf(tanha(fmaf(ybc, wo.y, bo.y)), 0.5f, 0.5f);
        o.z = fmaf(tanha(fmaf(ybc, wo.z, bo.z)), 0.5f, 0.5f);
        o.w = fmaf(tanha(fmaf(ybc, wo.w, bo.w)), 0.5f, 0.5f);
        *(float4*)(op + (size_t)cidx * OUTSZ) = o;
    }
}

// ---------------------------------------------------------------------------
extern "C" void kernel_launch(void* const* d_in, const int* in_sizes, int n_in,
                              void* d_out, int out_size)
{
    const float* x     = (const float*)d_in[0];
    const float* h     = (const float*)d_in[1];
    const float* c     = (const float*)d_in[2];
    const float* w_ih  = (const float*)d_in[3];
    const float* w_hh  = (const float*)d_in[4];
    const float* b_ih  = (const float*)d_in[5];
    const float* b_hh  = (const float*)d_in[6];
    const float* w_in  = (const float*)d_in[7];
    const float* b_in  = (const float*)d_in[8];
    const float* rb_w1 = (const float*)d_in[9];
    const float* rb_b1 = (const float*)d_in[10];
    const float* rb_w2 = (const float*)d_in[11];
    const float* rb_b2 = (const float*)d_in[12];
    const float* w_bn  = (const float*)d_in[13];
    const float* b_bn  = (const float*)d_in[14];
    const float* w_out = (const float*)d_in[15];
    const float* b_out = (const float*)d_in[16];
    float* out = (float*)d_out;

    k1_xw<<<2048, 256>>>(x, w_ih, b_ih, b_hh);
    k2_lstm<<<64, 32>>>(h, c, w_hh, out);
    k3_res<<<2048, 256>>>(w_in, b_in, rb_w1, rb_b1, rb_w2, rb_b2,
                          w_bn, b_bn, w_out, b_out, out);
}